// round 12
// baseline (speedup 1.0000x reference)
#include <cuda_runtime.h>
#include <cuda_bf16.h>

constexpr int B  = 2;
constexpr int CF = 64;
constexpr int H  = 64;
constexpr int W  = 2048;
constexpr int CC = 3;
constexpr int C0 = 16;
constexpr int C1 = 64;

constexpr int VEC = 4;            // pixels per thread (float4)
constexpr int TPB = 256;          // threads per block
constexpr int CF_PER_BLOCK = 8;   // feature channels per block
constexpr int CF_SPLITS = CF / CF_PER_BLOCK;  // 8

__device__ __forceinline__ float4 f4zero() { return make_float4(0.f, 0.f, 0.f, 0.f); }
__device__ __forceinline__ float4 fma4s(float s, float4 b, float4 c) {
    return make_float4(fmaf(s, b.x, c.x), fmaf(s, b.y, c.y),
                       fmaf(s, b.z, c.z), fmaf(s, b.w, c.w));
}
__device__ __forceinline__ float4 mul4ss(float s, float4 b) {
    return make_float4(s * b.x, s * b.y, s * b.z, s * b.w);
}

__global__ __launch_bounds__(TPB) void meta_fused_v11(
    const float* __restrict__ features,   // [B, CF, H, W]
    const float* __restrict__ coord,      // [B, CC, H, W]
    const float* __restrict__ w0,         // [C0, CC]
    const float* __restrict__ w1,         // [C1, C0]
    float* __restrict__ out)              // [B, CF*9, H, W]
{
    const int t       = threadIdx.x;
    const int lane    = t & 31;
    const int zb      = blockIdx.z;
    const int b       = zb / CF_SPLITS;
    const int cf_base = (zb % CF_SPLITS) * CF_PER_BLOCK;

    // Fold w1 @ w0 for this block's 8 output channels.
    __shared__ float sW[CF_PER_BLOCK * CC];
    if (t < CF_PER_BLOCK * CC) {
        const int o = cf_base + t / CC, c = t % CC;
        float s = 0.f;
        #pragma unroll
        for (int k = 0; k < C0; k++)
            s = fmaf(w1[o * C0 + k], w0[k * CC + c], s);
        sW[t] = s;
    }
    __syncthreads();

    const int g   = blockIdx.x * TPB + t;
    const int wp  = g * VEC;
    const int h   = blockIdx.y;
    const size_t chan = (size_t)H * W;
    const size_t hw   = (size_t)h * W + wp;

    const float* cbase = coord    + (size_t)b * CC * chan + hw;
    const float* fb    = features + ((size_t)b * CF + cf_base) * chan + hw;
    float*       ob    = out      + ((size_t)b * CF + cf_base) * 9 * chan + hw;

    const bool wl = (wp > 0);
    const bool wr = (wp + VEC < W);

    // Center coords; mask applied directly into rel below.
    float4 ctr[CC];
    bool dead[CC][4];
    #pragma unroll
    for (int c = 0; c < CC; c++) {
        ctr[c] = *(const float4*)(cbase + c * chan);
        dead[c][0] = (ctr[c].x == -1.f);
        dead[c][1] = (ctr[c].y == -1.f);
        dead[c][2] = (ctr[c].z == -1.f);
        dead[c][3] = (ctr[c].w == -1.f);
    }

    #pragma unroll
    for (int di = 0; di < 3; di++) {
        const int hh = h + di - 1;
        const bool rv = (hh >= 0) && (hh < H);
        const long roff = (long)(di - 1) * W;

        // Precompute masked rel[c][dj] once per di.
        float4 rel[CC][3];
        #pragma unroll
        for (int c = 0; c < CC; c++) {
            const float* p = cbase + c * chan + roff;
            const float4 c4 = rv ? *(const float4*)p : f4zero();
            float l = __shfl_up_sync(0xffffffffu, c4.w, 1);
            float r = __shfl_down_sync(0xffffffffu, c4.x, 1);
            if (lane == 0)  l = (rv && wl) ? __ldg(p - 1)   : 0.f;
            if (lane == 31) r = (rv && wr) ? __ldg(p + VEC) : 0.f;

            #pragma unroll
            for (int dj = 0; dj < 3; dj++) {
                float4 s;
                if (dj == 0)      s = make_float4(l,    c4.x, c4.y, c4.z);
                else if (dj == 1) s = c4;
                else              s = make_float4(c4.y, c4.z, c4.w, r);
                float4 rr;
                rr.x = dead[c][0] ? 0.f : (s.x - ctr[c].x);
                rr.y = dead[c][1] ? 0.f : (s.y - ctr[c].y);
                rr.z = dead[c][2] ? 0.f : (s.z - ctr[c].z);
                rr.w = dead[c][3] ? 0.f : (s.w - ctr[c].w);
                rel[c][dj] = rr;
            }
        }

        #pragma unroll 2
        for (int cf = 0; cf < CF_PER_BLOCK; cf++) {
            const float a0 = sW[cf * 3 + 0];
            const float a1 = sW[cf * 3 + 1];
            const float a2 = sW[cf * 3 + 2];

            // Feature row: one aligned LD.128 + shuffled edges.
            const float* fp = fb + (size_t)cf * chan + roff;
            const float4 f4 = rv ? *(const float4*)fp : f4zero();
            float fl = __shfl_up_sync(0xffffffffu, f4.w, 1);
            float fr = __shfl_down_sync(0xffffffffu, f4.x, 1);
            if (lane == 0)  fl = (rv && wl) ? __ldg(fp - 1)   : 0.f;
            if (lane == 31) fr = (rv && wr) ? __ldg(fp + VEC) : 0.f;

            float* oc = ob + (size_t)(cf * 9 + di * 3) * chan;

            #pragma unroll
            for (int dj = 0; dj < 3; dj++) {
                float4 Fv;
                if (dj == 0)      Fv = make_float4(fl,   f4.x, f4.y, f4.z);
                else if (dj == 1) Fv = f4;
                else              Fv = make_float4(f4.y, f4.z, f4.w, fr);

                const float4 wt = fma4s(a0, rel[0][dj],
                                   fma4s(a1, rel[1][dj],
                                   mul4ss(a2, rel[2][dj])));
                float4 o4;
                o4.x = Fv.x * fmaxf(wt.x, 0.f);
                o4.y = Fv.y * fmaxf(wt.y, 0.f);
                o4.z = Fv.z * fmaxf(wt.z, 0.f);
                o4.w = Fv.w * fmaxf(wt.w, 0.f);
                // A/B: plain STG.128 (default caching) vs prior __stcs —
                // let L2 aggregate writebacks lazily.
                *(float4*)(oc + (size_t)dj * chan) = o4;
            }
        }
    }
}

extern "C" void kernel_launch(void* const* d_in, const int* in_sizes, int n_in,
                              void* d_out, int out_size) {
    const float* features = (const float*)d_in[0];
    const float* coord    = (const float*)d_in[1];
    const float* w0       = (const float*)d_in[2];
    const float* w1       = (const float*)d_in[3];
    float* out = (float*)d_out;

    dim3 grid(W / (VEC * TPB), H, B * CF_SPLITS);   // (2, 64, 16) = 2048 blocks
    meta_fused_v11<<<grid, TPB>>>(features, coord, w0, w1, out);
}

// round 16
// speedup vs baseline: 1.0841x; 1.0841x over previous
#include <cuda_runtime.h>
#include <cuda_bf16.h>

constexpr int B  = 2;
constexpr int CF = 64;
constexpr int H  = 64;
constexpr int W  = 2048;
constexpr int CC = 3;
constexpr int C0 = 16;
constexpr int C1 = 64;

constexpr int VEC = 4;            // pixels per thread (float4)
constexpr int TPB = 256;          // threads per block
constexpr int CF_PER_BLOCK = 4;   // feature channels per block
constexpr int CF_SPLITS = CF / CF_PER_BLOCK;  // 16
constexpr int GX = W / (VEC * TPB);           // 2

__device__ __forceinline__ float4 f4zero() { return make_float4(0.f, 0.f, 0.f, 0.f); }
__device__ __forceinline__ float4 fma4s(float s, float4 b, float4 c) {
    return make_float4(fmaf(s, b.x, c.x), fmaf(s, b.y, c.y),
                       fmaf(s, b.z, c.z), fmaf(s, b.w, c.w));
}
__device__ __forceinline__ float4 mul4ss(float s, float4 b) {
    return make_float4(s * b.x, s * b.y, s * b.z, s * b.w);
}

__global__ __launch_bounds__(TPB) void meta_fused_v13(
    const float* __restrict__ features,   // [B, CF, H, W]
    const float* __restrict__ coord,      // [B, CC, H, W]
    const float* __restrict__ w0,         // [C0, CC]
    const float* __restrict__ w1,         // [C1, C0]
    float* __restrict__ out)              // [B, CF*9, H, W]
{
    const int t       = threadIdx.x;
    const int lane    = t & 31;
    const int zb      = blockIdx.z;
    const int b       = zb / CF_SPLITS;
    const int cf_base = (zb % CF_SPLITS) * CF_PER_BLOCK;

    // Fold w1 @ w0 for this block's 4 output channels.
    __shared__ float sW[CF_PER_BLOCK * CC];
    if (t < CF_PER_BLOCK * CC) {
        const int o = cf_base + t / CC, c = t % CC;
        float s = 0.f;
        #pragma unroll
        for (int k = 0; k < C0; k++)
            s = fmaf(w1[o * C0 + k], w0[k * CC + c], s);
        sW[t] = s;
    }
    __syncthreads();

    const int g   = blockIdx.x * TPB + t;
    const int wp  = g * VEC;
    const int h   = blockIdx.y;
    const size_t chan = (size_t)H * W;
    const size_t hw   = (size_t)h * W + wp;

    const float* cbase = coord    + (size_t)b * CC * chan + hw;
    const float* fb    = features + ((size_t)b * CF + cf_base) * chan + hw;
    float*       ob    = out      + ((size_t)b * CF + cf_base) * 9 * chan + hw;

    const bool wl = (wp > 0);
    const bool wr = (wp + VEC < W);

    // Center coords; mask applied directly into rel below.
    float4 ctr[CC];
    bool dead[CC][4];
    #pragma unroll
    for (int c = 0; c < CC; c++) {
        ctr[c] = *(const float4*)(cbase + c * chan);
        dead[c][0] = (ctr[c].x == -1.f);
        dead[c][1] = (ctr[c].y == -1.f);
        dead[c][2] = (ctr[c].z == -1.f);
        dead[c][3] = (ctr[c].w == -1.f);
    }

    #pragma unroll
    for (int di = 0; di < 3; di++) {
        const int hh = h + di - 1;
        const bool rv = (hh >= 0) && (hh < H);
        const long roff = (long)(di - 1) * W;

        // Precompute masked rel[c][dj] once per di.
        float4 rel[CC][3];
        #pragma unroll
        for (int c = 0; c < CC; c++) {
            const float* p = cbase + c * chan + roff;
            const float4 c4 = rv ? *(const float4*)p : f4zero();
            float l = __shfl_up_sync(0xffffffffu, c4.w, 1);
            float r = __shfl_down_sync(0xffffffffu, c4.x, 1);
            if (lane == 0)  l = (rv && wl) ? __ldg(p - 1)   : 0.f;
            if (lane == 31) r = (rv && wr) ? __ldg(p + VEC) : 0.f;

            #pragma unroll
            for (int dj = 0; dj < 3; dj++) {
                float4 s;
                if (dj == 0)      s = make_float4(l,    c4.x, c4.y, c4.z);
                else if (dj == 1) s = c4;
                else              s = make_float4(c4.y, c4.z, c4.w, r);
                float4 rr;
                rr.x = dead[c][0] ? 0.f : (s.x - ctr[c].x);
                rr.y = dead[c][1] ? 0.f : (s.y - ctr[c].y);
                rr.z = dead[c][2] ? 0.f : (s.z - ctr[c].z);
                rr.w = dead[c][3] ? 0.f : (s.w - ctr[c].w);
                rel[c][dj] = rr;
            }
        }

        #pragma unroll
        for (int cf = 0; cf < CF_PER_BLOCK; cf++) {
            const float a0 = sW[cf * 3 + 0];
            const float a1 = sW[cf * 3 + 1];
            const float a2 = sW[cf * 3 + 2];

            // Feature row: one aligned LD.128 + shuffled edges.
            const float* fp = fb + (size_t)cf * chan + roff;
            const float4 f4 = rv ? *(const float4*)fp : f4zero();
            float fl = __shfl_up_sync(0xffffffffu, f4.w, 1);
            float fr = __shfl_down_sync(0xffffffffu, f4.x, 1);
            if (lane == 0)  fl = (rv && wl) ? __ldg(fp - 1)   : 0.f;
            if (lane == 31) fr = (rv && wr) ? __ldg(fp + VEC) : 0.f;

            float* oc = ob + (size_t)(cf * 9 + di * 3) * chan;

            #pragma unroll
            for (int dj = 0; dj < 3; dj++) {
                float4 Fv;
                if (dj == 0)      Fv = make_float4(fl,   f4.x, f4.y, f4.z);
                else if (dj == 1) Fv = f4;
                else              Fv = make_float4(f4.y, f4.z, f4.w, fr);

                const float4 wt = fma4s(a0, rel[0][dj],
                                   fma4s(a1, rel[1][dj],
                                   mul4ss(a2, rel[2][dj])));
                float4 o4;
                o4.x = Fv.x * fmaxf(wt.x, 0.f);
                o4.y = Fv.y * fmaxf(wt.y, 0.f);
                o4.z = Fv.z * fmaxf(wt.z, 0.f);
                o4.w = Fv.w * fmaxf(wt.w, 0.f);
                __stcs((float4*)(oc + (size_t)dj * chan), o4);
            }
        }
    }
}

extern "C" void kernel_launch(void* const* d_in, const int* in_sizes, int n_in,
                              void* d_out, int out_size) {
    const float* features = (const float*)d_in[0];
    const float* coord    = (const float*)d_in[1];
    const float* w0       = (const float*)d_in[2];
    const float* w1       = (const float*)d_in[3];
    float* out = (float*)d_out;

    dim3 grid(GX, H, B * CF_SPLITS);   // (2, 64, 32) = 4096 blocks
    meta_fused_v13<<<grid, TPB>>>(features, coord, w0, w1, out);
}